// round 12
// baseline (speedup 1.0000x reference)
#include <cuda_runtime.h>
#include <cuda_bf16.h>
#include <math.h>

#define SQ   2048
#define DM   1024
#define NH   16
#define HD   64
#define NL   4
#define FF   4096
#define IND  64
#define OUTD 128

// smem layout (bf16 elems): AsH[2][128][40] AsL[2][128][40] BsH[2][32][136] BsL[2][32][136]
#define ASTG 5120            // 128*40 elems per A stage
#define BSTG 4352            // 32*136 elems per B stage
#define SMEM_BYTES 75776     // (2*ASTG*2 + 2*BSTG*2)*2

// ---------------- scratch (device globals; no allocation) ----------------
__device__ float g_h [SQ*DM];
__device__ float g_hn[SQ*DM];
__device__ float g_q [SQ*DM];
__device__ float g_k [SQ*DM];
__device__ float g_v [SQ*DM];
__device__ float g_o [SQ*DM];
__device__ float g_f1[SQ*FF];
__device__ float g_f3[SQ*FF];

__device__ __forceinline__ unsigned sptr(const void* p) {
    return (unsigned)__cvta_generic_to_shared(p);
}

#define MMA_BF16(d0,d1,d2,d3,a0,a1,a2,a3,b0,b1)                              \
    asm volatile("mma.sync.aligned.m16n8k16.row.col.f32.bf16.bf16.f32 "       \
                 "{%0,%1,%2,%3}, {%4,%5,%6,%7}, {%8,%9}, {%0,%1,%2,%3};"      \
                 : "+f"(d0), "+f"(d1), "+f"(d2), "+f"(d3)                     \
                 : "r"(a0), "r"(a1), "r"(a2), "r"(a3), "r"(b0), "r"(b1))

#define LDSM_X4(r0,r1,r2,r3,addr)                                             \
    asm volatile("ldmatrix.sync.aligned.m8n8.x4.shared.b16 {%0,%1,%2,%3}, [%4];" \
                 : "=r"(r0), "=r"(r1), "=r"(r2), "=r"(r3) : "r"(addr))

#define LDSM_X4T(r0,r1,r2,r3,addr)                                            \
    asm volatile("ldmatrix.sync.aligned.m8n8.x4.trans.shared.b16 {%0,%1,%2,%3}, [%4];" \
                 : "=r"(r0), "=r"(r1), "=r"(r2), "=r"(r3) : "r"(addr))

__device__ __forceinline__ float4 gate_load(const float* __restrict__ F1,
                                            const float* __restrict__ F3, size_t idx)
{
    float4 a = *(const float4*)&F1[idx];
    float4 g = *(const float4*)&F3[idx];
    a.x = (a.x / (1.0f + expf(-a.x))) * g.x;
    a.y = (a.y / (1.0f + expf(-a.y))) * g.y;
    a.z = (a.z / (1.0f + expf(-a.z))) * g.z;
    a.w = (a.w / (1.0f + expf(-a.w))) * g.w;
    return a;
}

// convert a prefetched fp32 tile to bf16 hi/lo and store into stage buffers
__device__ __forceinline__ void cvt_store_tile(
    __nv_bfloat16* __restrict__ aH, __nv_bfloat16* __restrict__ aL,
    __nv_bfloat16* __restrict__ bH, __nv_bfloat16* __restrict__ bL,
    const float4* areg, const float4* breg,
    int am, int ak, int bk, int bc)
{
    #pragma unroll
    for (int i = 0; i < 4; i++) {
        float av[4] = {areg[i].x, areg[i].y, areg[i].z, areg[i].w};
        __nv_bfloat16 h4[4], l4[4];
        #pragma unroll
        for (int e = 0; e < 4; e++) {
            h4[e] = __float2bfloat16_rn(av[e]);
            l4[e] = __float2bfloat16_rn(av[e] - __bfloat162float(h4[e]));
        }
        *(uint2*)&aH[(am + 32 * i) * 40 + ak] = *(uint2*)h4;
        *(uint2*)&aL[(am + 32 * i) * 40 + ak] = *(uint2*)l4;

        float bv[4] = {breg[i].x, breg[i].y, breg[i].z, breg[i].w};
        #pragma unroll
        for (int e = 0; e < 4; e++) {
            h4[e] = __float2bfloat16_rn(bv[e]);
            l4[e] = __float2bfloat16_rn(bv[e] - __bfloat162float(h4[e]));
        }
        *(uint2*)&bH[(bk + 8 * i) * 136 + bc] = *(uint2*)h4;
        *(uint2*)&bL[(bk + 8 * i) * 136 + bc] = *(uint2*)l4;
    }
}

// ---------------- bf16x3 tensor-core GEMM (R5 config), double-buffered ----
// C[M,N] = A'[M,K] @ B[K,N] (+bias / +residual), fp32 in memory.
// A' = silu(A)*G when G != nullptr, else A.
// acc += Ah*Bh + Ah*Bl + Al*Bh  (bf16 hi/lo split, fp32 accumulate)
// BM=BN=128, BK=32, 256 threads, warp grid 2x4 (warp tile 64x32).
// blockIdx.z selects (B,C). mode 0: plain  1: +bias[col]  2: +X[row*N+col]
__global__ __launch_bounds__(256)
void tgemm_kernel(const float* __restrict__ A, const float* __restrict__ G,
                  const float* __restrict__ B0, const float* __restrict__ B1,
                  const float* __restrict__ B2,
                  float* __restrict__ C0, float* __restrict__ C1, float* __restrict__ C2,
                  const float* __restrict__ X, int M, int N, int K, int mode)
{
    extern __shared__ char dynsmem[];
    const float* B = (blockIdx.z == 0) ? B0 : (blockIdx.z == 1) ? B1 : B2;
    float*       C = (blockIdx.z == 0) ? C0 : (blockIdx.z == 1) ? C1 : C2;

    __nv_bfloat16* sAH = (__nv_bfloat16*)dynsmem;   // [2][128][40]
    __nv_bfloat16* sAL = sAH + 2 * ASTG;
    __nv_bfloat16* sBH = sAL + 2 * ASTG;            // [2][32][136]
    __nv_bfloat16* sBL = sBH + 2 * BSTG;

    const int tid  = threadIdx.x;
    const int warp = tid >> 5;
    const int lane = tid & 31;

    const int bm = blockIdx.y * 128;
    const int bn = blockIdx.x * 128;
    const int mb = (warp >> 2) * 64;
    const int nb = (warp & 3) * 32;

    const int am = tid >> 3;            // 0..31 (A row; +32*i)
    const int ak = (tid & 7) * 4;       // 0..28
    const int bk = tid >> 5;            // 0..7  (B k row; +8*i)
    const int bc = (tid & 31) * 4;      // 0..124

    float acc[4][4][4];
    #pragma unroll
    for (int i = 0; i < 4; i++)
        #pragma unroll
        for (int j = 0; j < 4; j++)
            #pragma unroll
            for (int c = 0; c < 4; c++) acc[i][j][c] = 0.f;

    float4 areg[4], breg[4];
    #pragma unroll
    for (int i = 0; i < 4; i++) {
        size_t aidx = (size_t)(bm + am + 32 * i) * K + ak;
        areg[i] = G ? gate_load(A, G, aidx) : *(const float4*)&A[aidx];
        breg[i] = *(const float4*)&B[(size_t)(bk + 8 * i) * N + bn + bc];
    }
    cvt_store_tile(sAH, sAL, sBH, sBL, areg, breg, am, ak, bk, bc);
    __syncthreads();

    const unsigned smBase   = sptr(dynsmem);
    const unsigned aLaneOff = (unsigned)(lane & 15) * 80u + (unsigned)(lane >> 4) * 16u;
    const unsigned bLaneOff = (unsigned)(((lane >> 3) & 1) * 8 + (lane & 7)) * 272u
                            + (unsigned)(lane >> 4) * 16u;

    const int ktiles = K / 32;
    for (int kt = 0; kt < ktiles; kt++) {
        const int cur = kt & 1;

        if (kt + 1 < ktiles) {
            const int k0 = (kt + 1) * 32;
            #pragma unroll
            for (int i = 0; i < 4; i++) {
                size_t aidx = (size_t)(bm + am + 32 * i) * K + k0 + ak;
                areg[i] = G ? gate_load(A, G, aidx) : *(const float4*)&A[aidx];
                breg[i] = *(const float4*)&B[(size_t)(k0 + bk + 8 * i) * N + bn + bc];
            }
        }

        const unsigned aHb = smBase + (unsigned)cur * 10240u + aLaneOff;
        const unsigned bHb = smBase + 40960u + (unsigned)cur * 8704u + bLaneOff;
        #pragma unroll
        for (int kk = 0; kk < 32; kk += 16) {
            unsigned aH[4][4], aL[4][4], bH[4][2], bL[4][2];
            #pragma unroll
            for (int mt = 0; mt < 4; mt++) {
                unsigned ad = aHb + (unsigned)(mb + mt * 16) * 80u + (unsigned)kk * 2u;
                LDSM_X4(aH[mt][0], aH[mt][1], aH[mt][2], aH[mt][3], ad);
                LDSM_X4(aL[mt][0], aL[mt][1], aL[mt][2], aL[mt][3], ad + 20480u);
            }
            #pragma unroll
            for (int np = 0; np < 2; np++) {
                unsigned bd = bHb + (unsigned)kk * 272u + (unsigned)(nb + np * 16) * 2u;
                LDSM_X4T(bH[np*2][0], bH[np*2][1], bH[np*2+1][0], bH[np*2+1][1], bd);
                LDSM_X4T(bL[np*2][0], bL[np*2][1], bL[np*2+1][0], bL[np*2+1][1], bd + 17408u);
            }
            #pragma unroll
            for (int mt = 0; mt < 4; mt++)
                #pragma unroll
                for (int nt = 0; nt < 4; nt++) {
                    MMA_BF16(acc[mt][nt][0], acc[mt][nt][1], acc[mt][nt][2], acc[mt][nt][3],
                             aH[mt][0], aH[mt][1], aH[mt][2], aH[mt][3],
                             bH[nt][0], bH[nt][1]);
                    MMA_BF16(acc[mt][nt][0], acc[mt][nt][1], acc[mt][nt][2], acc[mt][nt][3],
                             aH[mt][0], aH[mt][1], aH[mt][2], aH[mt][3],
                             bL[nt][0], bL[nt][1]);
                    MMA_BF16(acc[mt][nt][0], acc[mt][nt][1], acc[mt][nt][2], acc[mt][nt][3],
                             aL[mt][0], aL[mt][1], aL[mt][2], aL[mt][3],
                             bH[nt][0], bH[nt][1]);
                }
        }

        if (kt + 1 < ktiles) {
            const int nxt = cur ^ 1;
            cvt_store_tile(sAH + nxt * ASTG, sAL + nxt * ASTG,
                           sBH + nxt * BSTG, sBL + nxt * BSTG,
                           areg, breg, am, ak, bk, bc);
        }
        __syncthreads();
    }

    // epilogue
    const int g = lane >> 2;
    const int t = lane & 3;
    #pragma unroll
    for (int mt = 0; mt < 4; mt++) {
        const int r0 = bm + mb + mt * 16 + g;
        const int r1 = r0 + 8;
        #pragma unroll
        for (int nt = 0; nt < 4; nt++) {
            const int c = bn + nb + nt * 8 + 2 * t;
            float2 v0 = make_float2(acc[mt][nt][0], acc[mt][nt][1]);
            float2 v1 = make_float2(acc[mt][nt][2], acc[mt][nt][3]);
            if (mode == 1) {
                float2 bb = *(const float2*)&X[c];
                v0.x += bb.x; v0.y += bb.y;
                v1.x += bb.x; v1.y += bb.y;
            } else if (mode == 2) {
                float2 x0 = *(const float2*)&X[(size_t)r0 * N + c];
                float2 x1 = *(const float2*)&X[(size_t)r1 * N + c];
                v0.x += x0.x; v0.y += x0.y;
                v1.x += x1.x; v1.y += x1.y;
            }
            *(float2*)&C[(size_t)r0 * N + c] = v0;
            *(float2*)&C[(size_t)r1 * N + c] = v1;
        }
    }
}

// ---------------- RMSNorm over D=1024 ----------------
__global__ void rmsnorm_kernel(const float* __restrict__ x, const float* __restrict__ w,
                               float* __restrict__ y)
{
    const int row = blockIdx.x;
    const float* xr = x + (size_t)row * DM;
    __shared__ float red[256];
    float s = 0.f;
    for (int i = threadIdx.x; i < DM; i += 256) { float v = xr[i]; s += v * v; }
    red[threadIdx.x] = s;
    __syncthreads();
    for (int st = 128; st > 0; st >>= 1) {
        if (threadIdx.x < st) red[threadIdx.x] += red[threadIdx.x + st];
        __syncthreads();
    }
    float scale = 1.0f / sqrtf(red[0] / (float)DM + 1e-5f);
    for (int i = threadIdx.x; i < DM; i += 256)
        y[(size_t)row * DM + i] = xr[i] * scale * w[i];
}

// ---------------- RoPE: one block per token, 512 threads ----------------
__global__ void rope_kernel(float* __restrict__ q, float* __restrict__ k,
                            const int* __restrict__ tok_id)
{
    const int s = blockIdx.x;
    const int tid = threadIdx.x;          // 512
    __shared__ float cs[32], sn[32];
    if (tid < 32) {
        const float t = (float)tok_id[s];
        const float inv = expf(-(float)tid * (9.210340371976184f / 32.0f));
        float ss, cc;
        sincosf(t * inv, &ss, &cc);
        cs[tid] = cc; sn[tid] = ss;
    }
    __syncthreads();
    const int h = tid >> 5, d = tid & 31;
    const size_t base = (size_t)s * DM + h * HD;
    const float c = cs[d], ssn = sn[d];
    float x1 = q[base + d], x2 = q[base + d + 32];
    q[base + d]      = x1 * c - x2 * ssn;
    q[base + d + 32] = x1 * ssn + x2 * c;
    x1 = k[base + d]; x2 = k[base + d + 32];
    k[base + d]      = x1 * c - x2 * ssn;
    k[base + d + 32] = x1 * ssn + x2 * c;
}

// ---------------- banded attention: block per (query s, head h), 128 thr --
__global__ void attn_kernel(const float* __restrict__ q, const float* __restrict__ k,
                            const float* __restrict__ v, const int* __restrict__ tok_id,
                            float* __restrict__ o)
{
    const int s = blockIdx.x, h = blockIdx.y;
    const int tid  = threadIdx.x;     // 0..127
    const int half = tid >> 6;
    const int d    = tid & 63;
    __shared__ float qs[HD];
    __shared__ float sc[256];
    __shared__ float red[128];
    __shared__ float part[2][HD];

    const int t    = tok_id[s];
    const int base = s - t;
    const int lo   = base + max(0, t - 127);
    const int hi   = base + min(255, t + 127);
    const int nk   = hi - lo + 1;
    const int hb   = h * HD;

    if (tid < HD) qs[tid] = q[(size_t)s * DM + hb + tid];
    __syncthreads();

    float lm = -1e30f;
    for (int j = tid; j < nk; j += 128) {
        const float* kr = k + (size_t)(lo + j) * DM + hb;
        float acc = 0.f;
        #pragma unroll
        for (int d2 = 0; d2 < HD; d2 += 4) {
            float4 kv = *(const float4*)(kr + d2);
            acc = fmaf(qs[d2 + 0], kv.x, acc);
            acc = fmaf(qs[d2 + 1], kv.y, acc);
            acc = fmaf(qs[d2 + 2], kv.z, acc);
            acc = fmaf(qs[d2 + 3], kv.w, acc);
        }
        sc[j] = acc * 0.125f;
        lm = fmaxf(lm, sc[j]);
    }
    red[tid] = lm;
    __syncthreads();
    for (int st = 64; st > 0; st >>= 1) {
        if (tid < st) red[tid] = fmaxf(red[tid], red[tid + st]);
        __syncthreads();
    }
    const float mx = red[0];
    __syncthreads();

    float ls = 0.f;
    for (int j = tid; j < nk; j += 128) {
        float e = expf(sc[j] - mx);
        sc[j] = e;
        ls += e;
    }
    red[tid] = ls;
    __syncthreads();
    for (int st = 64; st > 0; st >>= 1) {
        if (tid < st) red[tid] += red[tid + st];
        __syncthreads();
    }
    const float inv_sum = 1.0f / red[0];

    float a0 = 0.f, a1 = 0.f;
    int j = half;
    for (; j + 2 < nk; j += 4) {
        a0 = fmaf(sc[j],     v[(size_t)(lo + j)     * DM + hb + d], a0);
        a1 = fmaf(sc[j + 2], v[(size_t)(lo + j + 2) * DM + hb + d], a1);
    }
    for (; j < nk; j += 2)
        a0 = fmaf(sc[j], v[(size_t)(lo + j) * DM + hb + d], a0);
    part[half][d] = a0 + a1;
    __syncthreads();
    if (half == 0)
        o[(size_t)s * DM + hb + d] = (part[0][d] + part[1][d]) * inv_sum;
}

// ---------------- drivers ----------------
static inline void tgemm(const float* A, const float* B, float* C, const float* X,
                         int M, int N, int K, int mode, const float* G = nullptr)
{
    dim3 grid(N / 128, M / 128, 1);
    tgemm_kernel<<<grid, 256, SMEM_BYTES>>>(A, G, B, B, B, C, C, C, X, M, N, K, mode);
}
static inline void tgemm2(const float* A, const float* B0, const float* B1,
                          float* C0, float* C1, int M, int N, int K)
{
    dim3 grid(N / 128, M / 128, 2);
    tgemm_kernel<<<grid, 256, SMEM_BYTES>>>(A, nullptr, B0, B1, B1, C0, C1, C1,
                                            nullptr, M, N, K, 0);
}
static inline void tgemm3(const float* A, const float* B0, const float* B1, const float* B2,
                          float* C0, float* C1, float* C2, int M, int N, int K)
{
    dim3 grid(N / 128, M / 128, 3);
    tgemm_kernel<<<grid, 256, SMEM_BYTES>>>(A, nullptr, B0, B1, B2, C0, C1, C2,
                                            nullptr, M, N, K, 0);
}

extern "C" void kernel_launch(void* const* d_in, const int* in_sizes, int n_in,
                              void* d_out, int out_size)
{
    const float* x           = (const float*)d_in[0];
    const float* emb_w       = (const float*)d_in[1];
    const float* emb_b       = (const float*)d_in[2];
    const float* wq          = (const float*)d_in[3];
    const float* wk          = (const float*)d_in[4];
    const float* wv          = (const float*)d_in[5];
    const float* wo          = (const float*)d_in[6];
    const float* attn_norm_w = (const float*)d_in[7];
    const float* ffn_norm_w  = (const float*)d_in[8];
    const float* w1          = (const float*)d_in[9];
    const float* w2          = (const float*)d_in[10];
    const float* w3          = (const float*)d_in[11];
    const float* out_norm_w  = (const float*)d_in[12];
    const float* out_w       = (const float*)d_in[13];
    const int*   doc_id      = (const int*)d_in[14]; (void)doc_id;
    const int*   tok_id      = (const int*)d_in[15];
    float* out = (float*)d_out;

    cudaFuncSetAttribute(tgemm_kernel,
                         cudaFuncAttributeMaxDynamicSharedMemorySize, SMEM_BYTES);

    float *h, *hn, *q, *k, *v, *o, *f1, *f3;
    cudaGetSymbolAddress((void**)&h,  g_h);
    cudaGetSymbolAddress((void**)&hn, g_hn);
    cudaGetSymbolAddress((void**)&q,  g_q);
    cudaGetSymbolAddress((void**)&k,  g_k);
    cudaGetSymbolAddress((void**)&v,  g_v);
    cudaGetSymbolAddress((void**)&o,  g_o);
    cudaGetSymbolAddress((void**)&f1, g_f1);
    cudaGetSymbolAddress((void**)&f3, g_f3);

    // embed: h = x @ emb_w + emb_b
    tgemm(x, emb_w, h, emb_b, SQ, DM, IND, 1);

    for (int l = 0; l < NL; l++) {
        const float* wq_l = wq + (size_t)l * DM * DM;
        const float* wk_l = wk + (size_t)l * DM * DM;
        const float* wv_l = wv + (size_t)l * DM * DM;
        const float* wo_l = wo + (size_t)l * DM * DM;
        const float* anw  = attn_norm_w + (size_t)l * DM;
        const float* fnw  = ffn_norm_w  + (size_t)l * DM;
        const float* w1_l = w1 + (size_t)l * DM * FF;
        const float* w2_l = w2 + (size_t)l * FF * DM;
        const float* w3_l = w3 + (size_t)l * DM * FF;

        rmsnorm_kernel<<<SQ, 256>>>(h, anw, hn);
        tgemm3(hn, wq_l, wk_l, wv_l, q, k, v, SQ, DM, DM);

        rope_kernel<<<SQ, 512>>>(q, k, tok_id);
        attn_kernel<<<dim3(SQ, NH), 128>>>(q, k, v, tok_id, o);

        // h = h + o @ wo
        tgemm(o, wo_l, h, h, SQ, DM, DM, 2);

        rmsnorm_kernel<<<SQ, 256>>>(h, fnw, hn);
        tgemm2(hn, w1_l, w3_l, f1, f3, SQ, FF, DM);
        // h = h + (silu(f1)*f3) @ w2   (gate fused into A-load)
        tgemm(f1, w2_l, h, h, SQ, DM, FF, 2, f3);
    }

    rmsnorm_kernel<<<SQ, 256>>>(h, out_norm_w, hn);
    tgemm(hn, out_w, out, nullptr, SQ, OUTD, DM, 0);
}

// round 15
// speedup vs baseline: 1.3277x; 1.3277x over previous
#include <cuda_runtime.h>
#include <cuda_bf16.h>
#include <math.h>

#define SQ   2048
#define DM   1024
#define NH   16
#define HD   64
#define NL   4
#define FF   4096
#define IND  64
#define OUTD 128

// smem layout (bf16 elems): AsH[2][128][40] AsL[2][128][40] BsH[2][32][136] BsL[2][32][136]
#define ASTG 5120            // 128*40 elems per A stage
#define BSTG 4352            // 32*136 elems per B stage
#define SMEM_BYTES 75776     // (2*ASTG*2 + 2*BSTG*2)*2

// ---------------- scratch (device globals; no allocation) ----------------
__device__ float g_h [SQ*DM];
__device__ float g_hn[SQ*DM];
__device__ float g_q [SQ*DM];
__device__ float g_k [SQ*DM];
__device__ float g_v [SQ*DM];
__device__ float g_o [SQ*DM];
__device__ float g_f1[SQ*FF];
__device__ float g_f3[SQ*FF];

__device__ __forceinline__ unsigned sptr(const void* p) {
    return (unsigned)__cvta_generic_to_shared(p);
}

#define MMA_BF16(d0,d1,d2,d3,a0,a1,a2,a3,b0,b1)                              \
    asm volatile("mma.sync.aligned.m16n8k16.row.col.f32.bf16.bf16.f32 "       \
                 "{%0,%1,%2,%3}, {%4,%5,%6,%7}, {%8,%9}, {%0,%1,%2,%3};"      \
                 : "+f"(d0), "+f"(d1), "+f"(d2), "+f"(d3)                     \
                 : "r"(a0), "r"(a1), "r"(a2), "r"(a3), "r"(b0), "r"(b1))

#define LDSM_X4(r0,r1,r2,r3,addr)                                             \
    asm volatile("ldmatrix.sync.aligned.m8n8.x4.shared.b16 {%0,%1,%2,%3}, [%4];" \
                 : "=r"(r0), "=r"(r1), "=r"(r2), "=r"(r3) : "r"(addr))

#define LDSM_X4T(r0,r1,r2,r3,addr)                                            \
    asm volatile("ldmatrix.sync.aligned.m8n8.x4.trans.shared.b16 {%0,%1,%2,%3}, [%4];" \
                 : "=r"(r0), "=r"(r1), "=r"(r2), "=r"(r3) : "r"(addr))

// convert a prefetched fp32 tile to bf16 hi/lo and store into stage buffers
__device__ __forceinline__ void cvt_store_tile(
    __nv_bfloat16* __restrict__ aH, __nv_bfloat16* __restrict__ aL,
    __nv_bfloat16* __restrict__ bH, __nv_bfloat16* __restrict__ bL,
    const float4* areg, const float4* breg,
    int am, int ak, int bk, int bc)
{
    #pragma unroll
    for (int i = 0; i < 4; i++) {
        float av[4] = {areg[i].x, areg[i].y, areg[i].z, areg[i].w};
        __nv_bfloat16 h4[4], l4[4];
        #pragma unroll
        for (int e = 0; e < 4; e++) {
            h4[e] = __float2bfloat16_rn(av[e]);
            l4[e] = __float2bfloat16_rn(av[e] - __bfloat162float(h4[e]));
        }
        *(uint2*)&aH[(am + 32 * i) * 40 + ak] = *(uint2*)h4;
        *(uint2*)&aL[(am + 32 * i) * 40 + ak] = *(uint2*)l4;

        float bv[4] = {breg[i].x, breg[i].y, breg[i].z, breg[i].w};
        #pragma unroll
        for (int e = 0; e < 4; e++) {
            h4[e] = __float2bfloat16_rn(bv[e]);
            l4[e] = __float2bfloat16_rn(bv[e] - __bfloat162float(h4[e]));
        }
        *(uint2*)&bH[(bk + 8 * i) * 136 + bc] = *(uint2*)h4;
        *(uint2*)&bL[(bk + 8 * i) * 136 + bc] = *(uint2*)l4;
    }
}

// ---------------- bf16x3 tensor-core GEMM (exact R5 config) ---------------
// C[M,N] = A[M,K] @ B[K,N] (+bias / +residual), fp32 in memory.
// acc += Ah*Bh + Ah*Bl + Al*Bh  (bf16 hi/lo split, fp32 accumulate)
// BM=BN=128, BK=32, 256 threads, warp grid 2x4 (warp tile 64x32).
// blockIdx.z selects (B,C). mode 0: plain  1: +bias[col]  2: +X[row*N+col]
__global__ __launch_bounds__(256)
void tgemm_kernel(const float* __restrict__ A,
                  const float* __restrict__ B0, const float* __restrict__ B1,
                  const float* __restrict__ B2,
                  float* __restrict__ C0, float* __restrict__ C1, float* __restrict__ C2,
                  const float* __restrict__ X, int M, int N, int K, int mode)
{
    extern __shared__ char dynsmem[];
    const float* B = (blockIdx.z == 0) ? B0 : (blockIdx.z == 1) ? B1 : B2;
    float*       C = (blockIdx.z == 0) ? C0 : (blockIdx.z == 1) ? C1 : C2;

    __nv_bfloat16* sAH = (__nv_bfloat16*)dynsmem;   // [2][128][40]
    __nv_bfloat16* sAL = sAH + 2 * ASTG;
    __nv_bfloat16* sBH = sAL + 2 * ASTG;            // [2][32][136]
    __nv_bfloat16* sBL = sBH + 2 * BSTG;

    const int tid  = threadIdx.x;
    const int warp = tid >> 5;
    const int lane = tid & 31;

    const int bm = blockIdx.y * 128;
    const int bn = blockIdx.x * 128;
    const int mb = (warp >> 2) * 64;
    const int nb = (warp & 3) * 32;

    const int am = tid >> 3;            // 0..31 (A row; +32*i)
    const int ak = (tid & 7) * 4;       // 0..28
    const int bk = tid >> 5;            // 0..7  (B k row; +8*i)
    const int bc = (tid & 31) * 4;      // 0..124

    float acc[4][4][4];
    #pragma unroll
    for (int i = 0; i < 4; i++)
        #pragma unroll
        for (int j = 0; j < 4; j++)
            #pragma unroll
            for (int c = 0; c < 4; c++) acc[i][j][c] = 0.f;

    float4 areg[4], breg[4];
    #pragma unroll
    for (int i = 0; i < 4; i++) {
        areg[i] = *(const float4*)&A[(size_t)(bm + am + 32 * i) * K + ak];
        breg[i] = *(const float4*)&B[(size_t)(bk + 8 * i) * N + bn + bc];
    }
    cvt_store_tile(sAH, sAL, sBH, sBL, areg, breg, am, ak, bk, bc);
    __syncthreads();

    const unsigned smBase   = sptr(dynsmem);
    const unsigned aLaneOff = (unsigned)(lane & 15) * 80u + (unsigned)(lane >> 4) * 16u;
    const unsigned bLaneOff = (unsigned)(((lane >> 3) & 1) * 8 + (lane & 7)) * 272u
                            + (unsigned)(lane >> 4) * 16u;

    const int ktiles = K / 32;
    for (int kt = 0; kt < ktiles; kt++) {
        const int cur = kt & 1;

        if (kt + 1 < ktiles) {
            const int k0 = (kt + 1) * 32;
            #pragma unroll
            for (int i = 0; i < 4; i++) {
                areg[i] = *(const float4*)&A[(size_t)(bm + am + 32 * i) * K + k0 + ak];
                breg[i] = *(const float4*)&B[(size_t)(k0 + bk + 8 * i) * N + bn + bc];
            }
        }

        const unsigned aHb = smBase + (unsigned)cur * 10240u + aLaneOff;
        const unsigned bHb = smBase + 40960u + (unsigned)cur * 8704u + bLaneOff;
        #pragma unroll
        for (int kk = 0; kk < 32; kk += 16) {
            unsigned aH[4][4], aL[4][4], bH[4][2], bL[4][2];
            #pragma unroll
            for (int mt = 0; mt < 4; mt++) {
                unsigned ad = aHb + (unsigned)(mb + mt * 16) * 80u + (unsigned)kk * 2u;
                LDSM_X4(aH[mt][0], aH[mt][1], aH[mt][2], aH[mt][3], ad);
                LDSM_X4(aL[mt][0], aL[mt][1], aL[mt][2], aL[mt][3], ad + 20480u);
            }
            #pragma unroll
            for (int np = 0; np < 2; np++) {
                unsigned bd = bHb + (unsigned)kk * 272u + (unsigned)(nb + np * 16) * 2u;
                LDSM_X4T(bH[np*2][0], bH[np*2][1], bH[np*2+1][0], bH[np*2+1][1], bd);
                LDSM_X4T(bL[np*2][0], bL[np*2][1], bL[np*2+1][0], bL[np*2+1][1], bd + 17408u);
            }
            #pragma unroll
            for (int mt = 0; mt < 4; mt++)
                #pragma unroll
                for (int nt = 0; nt < 4; nt++) {
                    MMA_BF16(acc[mt][nt][0], acc[mt][nt][1], acc[mt][nt][2], acc[mt][nt][3],
                             aH[mt][0], aH[mt][1], aH[mt][2], aH[mt][3],
                             bH[nt][0], bH[nt][1]);
                    MMA_BF16(acc[mt][nt][0], acc[mt][nt][1], acc[mt][nt][2], acc[mt][nt][3],
                             aH[mt][0], aH[mt][1], aH[mt][2], aH[mt][3],
                             bL[nt][0], bL[nt][1]);
                    MMA_BF16(acc[mt][nt][0], acc[mt][nt][1], acc[mt][nt][2], acc[mt][nt][3],
                             aL[mt][0], aL[mt][1], aL[mt][2], aL[mt][3],
                             bH[nt][0], bH[nt][1]);
                }
        }

        if (kt + 1 < ktiles) {
            const int nxt = cur ^ 1;
            cvt_store_tile(sAH + nxt * ASTG, sAL + nxt * ASTG,
                           sBH + nxt * BSTG, sBL + nxt * BSTG,
                           areg, breg, am, ak, bk, bc);
        }
        __syncthreads();
    }

    // epilogue
    const int g = lane >> 2;
    const int t = lane & 3;
    #pragma unroll
    for (int mt = 0; mt < 4; mt++) {
        const int r0 = bm + mb + mt * 16 + g;
        const int r1 = r0 + 8;
        #pragma unroll
        for (int nt = 0; nt < 4; nt++) {
            const int c = bn + nb + nt * 8 + 2 * t;
            float2 v0 = make_float2(acc[mt][nt][0], acc[mt][nt][1]);
            float2 v1 = make_float2(acc[mt][nt][2], acc[mt][nt][3]);
            if (mode == 1) {
                float2 bb = *(const float2*)&X[c];
                v0.x += bb.x; v0.y += bb.y;
                v1.x += bb.x; v1.y += bb.y;
            } else if (mode == 2) {
                float2 x0 = *(const float2*)&X[(size_t)r0 * N + c];
                float2 x1 = *(const float2*)&X[(size_t)r1 * N + c];
                v0.x += x0.x; v0.y += x0.y;
                v1.x += x1.x; v1.y += x1.y;
            }
            *(float2*)&C[(size_t)r0 * N + c] = v0;
            *(float2*)&C[(size_t)r1 * N + c] = v1;
        }
    }
}

// ---------------- RMSNorm over D=1024 ----------------
__global__ void rmsnorm_kernel(const float* __restrict__ x, const float* __restrict__ w,
                               float* __restrict__ y)
{
    const int row = blockIdx.x;
    const float* xr = x + (size_t)row * DM;
    __shared__ float red[256];
    float s = 0.f;
    for (int i = threadIdx.x; i < DM; i += 256) { float v = xr[i]; s += v * v; }
    red[threadIdx.x] = s;
    __syncthreads();
    for (int st = 128; st > 0; st >>= 1) {
        if (threadIdx.x < st) red[threadIdx.x] += red[threadIdx.x + st];
        __syncthreads();
    }
    float scale = 1.0f / sqrtf(red[0] / (float)DM + 1e-5f);
    for (int i = threadIdx.x; i < DM; i += 256)
        y[(size_t)row * DM + i] = xr[i] * scale * w[i];
}

// ---------------- RoPE: one block per token, 512 threads ----------------
__global__ void rope_kernel(float* __restrict__ q, float* __restrict__ k,
                            const int* __restrict__ tok_id)
{
    const int s = blockIdx.x;
    const int tid = threadIdx.x;          // 512
    __shared__ float cs[32], sn[32];
    if (tid < 32) {
        const float t = (float)tok_id[s];
        const float inv = expf(-(float)tid * (9.210340371976184f / 32.0f));
        float ss, cc;
        sincosf(t * inv, &ss, &cc);
        cs[tid] = cc; sn[tid] = ss;
    }
    __syncthreads();
    const int h = tid >> 5, d = tid & 31;
    const size_t base = (size_t)s * DM + h * HD;
    const float c = cs[d], ssn = sn[d];
    float x1 = q[base + d], x2 = q[base + d + 32];
    q[base + d]      = x1 * c - x2 * ssn;
    q[base + d + 32] = x1 * ssn + x2 * c;
    x1 = k[base + d]; x2 = k[base + d + 32];
    k[base + d]      = x1 * c - x2 * ssn;
    k[base + d + 32] = x1 * ssn + x2 * c;
}

// ---------------- banded attention: block per (query s, head h), 128 thr --
__global__ void attn_kernel(const float* __restrict__ q, const float* __restrict__ k,
                            const float* __restrict__ v, const int* __restrict__ tok_id,
                            float* __restrict__ o)
{
    const int s = blockIdx.x, h = blockIdx.y;
    const int tid  = threadIdx.x;     // 0..127
    const int half = tid >> 6;
    const int d    = tid & 63;
    __shared__ float qs[HD];
    __shared__ float sc[256];
    __shared__ float red[128];
    __shared__ float part[2][HD];

    const int t    = tok_id[s];
    const int base = s - t;
    const int lo   = base + max(0, t - 127);
    const int hi   = base + min(255, t + 127);
    const int nk   = hi - lo + 1;
    const int hb   = h * HD;

    if (tid < HD) qs[tid] = q[(size_t)s * DM + hb + tid];
    __syncthreads();

    float lm = -1e30f;
    for (int j = tid; j < nk; j += 128) {
        const float* kr = k + (size_t)(lo + j) * DM + hb;
        float acc = 0.f;
        #pragma unroll
        for (int d2 = 0; d2 < HD; d2 += 4) {
            float4 kv = *(const float4*)(kr + d2);
            acc = fmaf(qs[d2 + 0], kv.x, acc);
            acc = fmaf(qs[d2 + 1], kv.y, acc);
            acc = fmaf(qs[d2 + 2], kv.z, acc);
            acc = fmaf(qs[d2 + 3], kv.w, acc);
        }
        sc[j] = acc * 0.125f;
        lm = fmaxf(lm, sc[j]);
    }
    red[tid] = lm;
    __syncthreads();
    for (int st = 64; st > 0; st >>= 1) {
        if (tid < st) red[tid] = fmaxf(red[tid], red[tid + st]);
        __syncthreads();
    }
    const float mx = red[0];
    __syncthreads();

    float ls = 0.f;
    for (int j = tid; j < nk; j += 128) {
        float e = expf(sc[j] - mx);
        sc[j] = e;
        ls += e;
    }
    red[tid] = ls;
    __syncthreads();
    for (int st = 64; st > 0; st >>= 1) {
        if (tid < st) red[tid] += red[tid + st];
        __syncthreads();
    }
    const float inv_sum = 1.0f / red[0];

    float a0 = 0.f, a1 = 0.f;
    int j = half;
    for (; j + 2 < nk; j += 4) {
        a0 = fmaf(sc[j],     v[(size_t)(lo + j)     * DM + hb + d], a0);
        a1 = fmaf(sc[j + 2], v[(size_t)(lo + j + 2) * DM + hb + d], a1);
    }
    for (; j < nk; j += 2)
        a0 = fmaf(sc[j], v[(size_t)(lo + j) * DM + hb + d], a0);
    part[half][d] = a0 + a1;
    __syncthreads();
    if (half == 0)
        o[(size_t)s * DM + hb + d] = (part[0][d] + part[1][d]) * inv_sum;
}

// ---------------- SwiGLU gate: f1 = silu(f1) * f3 (float4) ----------------
__global__ void silu_mul_kernel(float* __restrict__ f1, const float* __restrict__ f3, int n4)
{
    int i = blockIdx.x * blockDim.x + threadIdx.x;
    if (i < n4) {
        float4 a = ((const float4*)f1)[i];
        float4 g = ((const float4*)f3)[i];
        a.x = (a.x / (1.0f + expf(-a.x))) * g.x;
        a.y = (a.y / (1.0f + expf(-a.y))) * g.y;
        a.z = (a.z / (1.0f + expf(-a.z))) * g.z;
        a.w = (a.w / (1.0f + expf(-a.w))) * g.w;
        ((float4*)f1)[i] = a;
    }
}

// ---------------- drivers ----------------
static inline void tgemm(const float* A, const float* B, float* C, const float* X,
                         int M, int N, int K, int mode)
{
    dim3 grid(N / 128, M / 128, 1);
    tgemm_kernel<<<grid, 256, SMEM_BYTES>>>(A, B, B, B, C, C, C, X, M, N, K, mode);
}
static inline void tgemm2(const float* A, const float* B0, const float* B1,
                          float* C0, float* C1, int M, int N, int K)
{
    dim3 grid(N / 128, M / 128, 2);
    tgemm_kernel<<<grid, 256, SMEM_BYTES>>>(A, B0, B1, B1, C0, C1, C1, nullptr, M, N, K, 0);
}
static inline void tgemm3(const float* A, const float* B0, const float* B1, const float* B2,
                          float* C0, float* C1, float* C2, int M, int N, int K)
{
    dim3 grid(N / 128, M / 128, 3);
    tgemm_kernel<<<grid, 256, SMEM_BYTES>>>(A, B0, B1, B2, C0, C1, C2, nullptr, M, N, K, 0);
}

extern "C" void kernel_launch(void* const* d_in, const int* in_sizes, int n_in,
                              void* d_out, int out_size)
{
    const float* x           = (const float*)d_in[0];
    const float* emb_w       = (const float*)d_in[1];
    const float* emb_b       = (const float*)d_in[2];
    const float* wq          = (const float*)d_in[3];
    const float* wk          = (const float*)d_in[4];
    const float* wv          = (const float*)d_in[5];
    const float* wo          = (const float*)d_in[6];
    const float* attn_norm_w = (const float*)d_in[7];
    const float* ffn_norm_w  = (const float*)d_in[8];
    const float* w1          = (const float*)d_in[9];
    const float* w2          = (const float*)d_in[10];
    const float* w3          = (const float*)d_in[11];
    const float* out_norm_w  = (const float*)d_in[12];
    const float* out_w       = (const float*)d_in[13];
    const int*   doc_id      = (const int*)d_in[14]; (void)doc_id;
    const int*   tok_id      = (const int*)d_in[15];
    float* out = (float*)d_out;

    cudaFuncSetAttribute(tgemm_kernel,
                         cudaFuncAttributeMaxDynamicSharedMemorySize, SMEM_BYTES);

    float *h, *hn, *q, *k, *v, *o, *f1, *f3;
    cudaGetSymbolAddress((void**)&h,  g_h);
    cudaGetSymbolAddress((void**)&hn, g_hn);
    cudaGetSymbolAddress((void**)&q,  g_q);
    cudaGetSymbolAddress((void**)&k,  g_k);
    cudaGetSymbolAddress((void**)&v,  g_v);
    cudaGetSymbolAddress((void**)&o,  g_o);
    cudaGetSymbolAddress((void**)&f1, g_f1);
    cudaGetSymbolAddress((void**)&f3, g_f3);

    // embed: h = x @ emb_w + emb_b
    tgemm(x, emb_w, h, emb_b, SQ, DM, IND, 1);

    for (int l = 0; l < NL; l++) {
        const float* wq_l = wq + (size_t)l * DM * DM;
        const float* wk_l = wk + (size_t)l * DM * DM;
        const float* wv_l = wv + (size_t)l * DM * DM;
        const float* wo_l = wo + (size_t)l * DM * DM;
        const float* anw  = attn_norm_w + (size_t)l * DM;
        const float* fnw  = ffn_norm_w  + (size_t)l * DM;
        const float* w1_l = w1 + (size_t)l * DM * FF;
        const float* w2_l = w2 + (size_t)l * FF * DM;
        const float* w3_l = w3 + (size_t)l * DM * FF;

        rmsnorm_kernel<<<SQ, 256>>>(h, anw, hn);
        tgemm3(hn, wq_l, wk_l, wv_l, q, k, v, SQ, DM, DM);

        rope_kernel<<<SQ, 512>>>(q, k, tok_id);
        attn_kernel<<<dim3(SQ, NH), 128>>>(q, k, v, tok_id, o);

        // h = h + o @ wo
        tgemm(o, wo_l, h, h, SQ, DM, DM, 2);

        rmsnorm_kernel<<<SQ, 256>>>(h, fnw, hn);
        tgemm2(hn, w1_l, w3_l, f1, f3, SQ, FF, DM);
        silu_mul_kernel<<<(SQ * FF / 4 + 255) / 256, 256>>>(f1, f3, SQ * FF / 4);
        // h = h + (silu(f1)*f3) @ w2
        tgemm(f1, w2_l, h, h, SQ, DM, FF, 2);
    }

    rmsnorm_kernel<<<SQ, 256>>>(h, out_norm_w, hn);
    tgemm(hn, out_w, out, nullptr, SQ, OUTD, DM, 0);
}

// round 16
// speedup vs baseline: 1.9269x; 1.4513x over previous
#include <cuda_runtime.h>
#include <cuda_bf16.h>
#include <math.h>

#define SQ   2048
#define DM   1024
#define NH   16
#define HD   64
#define NL   4
#define FF   4096
#define IND  64
#define OUTD 128
#define NDOC 8

// smem layout (bf16 elems): AsH[2][128][40] AsL[2][128][40] BsH[2][32][136] BsL[2][32][136]
#define ASTG 5120            // 128*40 elems per A stage
#define BSTG 4352            // 32*136 elems per B stage
#define SMEM_BYTES 75776     // (2*ASTG*2 + 2*BSTG*2)*2

// attention smem: Qs[256][64] + Ks[256][68] + Vs[256][64] + Ps[8][2][256] + tok[256]
#define ATTN_SMEM (65536 + 69632 + 65536 + 16384 + 1024)   // 218112 B

// ---------------- scratch (device globals; no allocation) ----------------
__device__ float g_h [SQ*DM];
__device__ float g_hn[SQ*DM];
__device__ float g_q [SQ*DM];
__device__ float g_k [SQ*DM];
__device__ float g_v [SQ*DM];
__device__ float g_o [SQ*DM];
__device__ float g_f1[SQ*FF];
__device__ float g_f3[SQ*FF];

__device__ __forceinline__ unsigned sptr(const void* p) {
    return (unsigned)__cvta_generic_to_shared(p);
}

#define MMA_BF16(d0,d1,d2,d3,a0,a1,a2,a3,b0,b1)                              \
    asm volatile("mma.sync.aligned.m16n8k16.row.col.f32.bf16.bf16.f32 "       \
                 "{%0,%1,%2,%3}, {%4,%5,%6,%7}, {%8,%9}, {%0,%1,%2,%3};"      \
                 : "+f"(d0), "+f"(d1), "+f"(d2), "+f"(d3)                     \
                 : "r"(a0), "r"(a1), "r"(a2), "r"(a3), "r"(b0), "r"(b1))

#define LDSM_X4(r0,r1,r2,r3,addr)                                             \
    asm volatile("ldmatrix.sync.aligned.m8n8.x4.shared.b16 {%0,%1,%2,%3}, [%4];" \
                 : "=r"(r0), "=r"(r1), "=r"(r2), "=r"(r3) : "r"(addr))

#define LDSM_X4T(r0,r1,r2,r3,addr)                                            \
    asm volatile("ldmatrix.sync.aligned.m8n8.x4.trans.shared.b16 {%0,%1,%2,%3}, [%4];" \
                 : "=r"(r0), "=r"(r1), "=r"(r2), "=r"(r3) : "r"(addr))

// convert a prefetched fp32 tile to bf16 hi/lo and store into stage buffers
__device__ __forceinline__ void cvt_store_tile(
    __nv_bfloat16* __restrict__ aH, __nv_bfloat16* __restrict__ aL,
    __nv_bfloat16* __restrict__ bH, __nv_bfloat16* __restrict__ bL,
    const float4* areg, const float4* breg,
    int am, int ak, int bk, int bc)
{
    #pragma unroll
    for (int i = 0; i < 4; i++) {
        float av[4] = {areg[i].x, areg[i].y, areg[i].z, areg[i].w};
        __nv_bfloat16 h4[4], l4[4];
        #pragma unroll
        for (int e = 0; e < 4; e++) {
            h4[e] = __float2bfloat16_rn(av[e]);
            l4[e] = __float2bfloat16_rn(av[e] - __bfloat162float(h4[e]));
        }
        *(uint2*)&aH[(am + 32 * i) * 40 + ak] = *(uint2*)h4;
        *(uint2*)&aL[(am + 32 * i) * 40 + ak] = *(uint2*)l4;

        float bv[4] = {breg[i].x, breg[i].y, breg[i].z, breg[i].w};
        #pragma unroll
        for (int e = 0; e < 4; e++) {
            h4[e] = __float2bfloat16_rn(bv[e]);
            l4[e] = __float2bfloat16_rn(bv[e] - __bfloat162float(h4[e]));
        }
        *(uint2*)&bH[(bk + 8 * i) * 136 + bc] = *(uint2*)h4;
        *(uint2*)&bL[(bk + 8 * i) * 136 + bc] = *(uint2*)l4;
    }
}

// ---------------- bf16x3 tensor-core GEMM (exact R5 config) ---------------
__global__ __launch_bounds__(256)
void tgemm_kernel(const float* __restrict__ A,
                  const float* __restrict__ B0, const float* __restrict__ B1,
                  const float* __restrict__ B2,
                  float* __restrict__ C0, float* __restrict__ C1, float* __restrict__ C2,
                  const float* __restrict__ X, int M, int N, int K, int mode)
{
    extern __shared__ char dynsmem[];
    const float* B = (blockIdx.z == 0) ? B0 : (blockIdx.z == 1) ? B1 : B2;
    float*       C = (blockIdx.z == 0) ? C0 : (blockIdx.z == 1) ? C1 : C2;

    __nv_bfloat16* sAH = (__nv_bfloat16*)dynsmem;   // [2][128][40]
    __nv_bfloat16* sAL = sAH + 2 * ASTG;
    __nv_bfloat16* sBH = sAL + 2 * ASTG;            // [2][32][136]
    __nv_bfloat16* sBL = sBH + 2 * BSTG;

    const int tid  = threadIdx.x;
    const int warp = tid >> 5;
    const int lane = tid & 31;

    const int bm = blockIdx.y * 128;
    const int bn = blockIdx.x * 128;
    const int mb = (warp >> 2) * 64;
    const int nb = (warp & 3) * 32;

    const int am = tid >> 3;
    const int ak = (tid & 7) * 4;
    const int bk = tid >> 5;
    const int bc = (tid & 31) * 4;

    float acc[4][4][4];
    #pragma unroll
    for (int i = 0; i < 4; i++)
        #pragma unroll
        for (int j = 0; j < 4; j++)
            #pragma unroll
            for (int c = 0; c < 4; c++) acc[i][j][c] = 0.f;

    float4 areg[4], breg[4];
    #pragma unroll
    for (int i = 0; i < 4; i++) {
        areg[i] = *(const float4*)&A[(size_t)(bm + am + 32 * i) * K + ak];
        breg[i] = *(const float4*)&B[(size_t)(bk + 8 * i) * N + bn + bc];
    }
    cvt_store_tile(sAH, sAL, sBH, sBL, areg, breg, am, ak, bk, bc);
    __syncthreads();

    const unsigned smBase   = sptr(dynsmem);
    const unsigned aLaneOff = (unsigned)(lane & 15) * 80u + (unsigned)(lane >> 4) * 16u;
    const unsigned bLaneOff = (unsigned)(((lane >> 3) & 1) * 8 + (lane & 7)) * 272u
                            + (unsigned)(lane >> 4) * 16u;

    const int ktiles = K / 32;
    for (int kt = 0; kt < ktiles; kt++) {
        const int cur = kt & 1;

        if (kt + 1 < ktiles) {
            const int k0 = (kt + 1) * 32;
            #pragma unroll
            for (int i = 0; i < 4; i++) {
                areg[i] = *(const float4*)&A[(size_t)(bm + am + 32 * i) * K + k0 + ak];
                breg[i] = *(const float4*)&B[(size_t)(k0 + bk + 8 * i) * N + bn + bc];
            }
        }

        const unsigned aHb = smBase + (unsigned)cur * 10240u + aLaneOff;
        const unsigned bHb = smBase + 40960u + (unsigned)cur * 8704u + bLaneOff;
        #pragma unroll
        for (int kk = 0; kk < 32; kk += 16) {
            unsigned aH[4][4], aL[4][4], bH[4][2], bL[4][2];
            #pragma unroll
            for (int mt = 0; mt < 4; mt++) {
                unsigned ad = aHb + (unsigned)(mb + mt * 16) * 80u + (unsigned)kk * 2u;
                LDSM_X4(aH[mt][0], aH[mt][1], aH[mt][2], aH[mt][3], ad);
                LDSM_X4(aL[mt][0], aL[mt][1], aL[mt][2], aL[mt][3], ad + 20480u);
            }
            #pragma unroll
            for (int np = 0; np < 2; np++) {
                unsigned bd = bHb + (unsigned)kk * 272u + (unsigned)(nb + np * 16) * 2u;
                LDSM_X4T(bH[np*2][0], bH[np*2][1], bH[np*2+1][0], bH[np*2+1][1], bd);
                LDSM_X4T(bL[np*2][0], bL[np*2][1], bL[np*2+1][0], bL[np*2+1][1], bd + 17408u);
            }
            #pragma unroll
            for (int mt = 0; mt < 4; mt++)
                #pragma unroll
                for (int nt = 0; nt < 4; nt++) {
                    MMA_BF16(acc[mt][nt][0], acc[mt][nt][1], acc[mt][nt][2], acc[mt][nt][3],
                             aH[mt][0], aH[mt][1], aH[mt][2], aH[mt][3],
                             bH[nt][0], bH[nt][1]);
                    MMA_BF16(acc[mt][nt][0], acc[mt][nt][1], acc[mt][nt][2], acc[mt][nt][3],
                             aH[mt][0], aH[mt][1], aH[mt][2], aH[mt][3],
                             bL[nt][0], bL[nt][1]);
                    MMA_BF16(acc[mt][nt][0], acc[mt][nt][1], acc[mt][nt][2], acc[mt][nt][3],
                             aL[mt][0], aL[mt][1], aL[mt][2], aL[mt][3],
                             bH[nt][0], bH[nt][1]);
                }
        }

        if (kt + 1 < ktiles) {
            const int nxt = cur ^ 1;
            cvt_store_tile(sAH + nxt * ASTG, sAL + nxt * ASTG,
                           sBH + nxt * BSTG, sBL + nxt * BSTG,
                           areg, breg, am, ak, bk, bc);
        }
        __syncthreads();
    }

    const int g = lane >> 2;
    const int t = lane & 3;
    #pragma unroll
    for (int mt = 0; mt < 4; mt++) {
        const int r0 = bm + mb + mt * 16 + g;
        const int r1 = r0 + 8;
        #pragma unroll
        for (int nt = 0; nt < 4; nt++) {
            const int c = bn + nb + nt * 8 + 2 * t;
            float2 v0 = make_float2(acc[mt][nt][0], acc[mt][nt][1]);
            float2 v1 = make_float2(acc[mt][nt][2], acc[mt][nt][3]);
            if (mode == 1) {
                float2 bb = *(const float2*)&X[c];
                v0.x += bb.x; v0.y += bb.y;
                v1.x += bb.x; v1.y += bb.y;
            } else if (mode == 2) {
                float2 x0 = *(const float2*)&X[(size_t)r0 * N + c];
                float2 x1 = *(const float2*)&X[(size_t)r1 * N + c];
                v0.x += x0.x; v0.y += x0.y;
                v1.x += x1.x; v1.y += x1.y;
            }
            *(float2*)&C[(size_t)r0 * N + c] = v0;
            *(float2*)&C[(size_t)r1 * N + c] = v1;
        }
    }
}

// ---------------- RMSNorm over D=1024 ----------------
__global__ void rmsnorm_kernel(const float* __restrict__ x, const float* __restrict__ w,
                               float* __restrict__ y)
{
    const int row = blockIdx.x;
    const float* xr = x + (size_t)row * DM;
    __shared__ float red[256];
    float s = 0.f;
    for (int i = threadIdx.x; i < DM; i += 256) { float v = xr[i]; s += v * v; }
    red[threadIdx.x] = s;
    __syncthreads();
    for (int st = 128; st > 0; st >>= 1) {
        if (threadIdx.x < st) red[threadIdx.x] += red[threadIdx.x + st];
        __syncthreads();
    }
    float scale = 1.0f / sqrtf(red[0] / (float)DM + 1e-5f);
    for (int i = threadIdx.x; i < DM; i += 256)
        y[(size_t)row * DM + i] = xr[i] * scale * w[i];
}

// ---------------- RoPE: one block per token, 512 threads ----------------
__global__ void rope_kernel(float* __restrict__ q, float* __restrict__ k,
                            const int* __restrict__ tok_id)
{
    const int s = blockIdx.x;
    const int tid = threadIdx.x;          // 512
    __shared__ float cs[32], sn[32];
    if (tid < 32) {
        const float t = (float)tok_id[s];
        const float inv = expf(-(float)tid * (9.210340371976184f / 32.0f));
        float ss, cc;
        sincosf(t * inv, &ss, &cc);
        cs[tid] = cc; sn[tid] = ss;
    }
    __syncthreads();
    const int h = tid >> 5, d = tid & 31;
    const size_t base = (size_t)s * DM + h * HD;
    const float c = cs[d], ssn = sn[d];
    float x1 = q[base + d], x2 = q[base + d + 32];
    q[base + d]      = x1 * c - x2 * ssn;
    q[base + d + 32] = x1 * ssn + x2 * c;
    x1 = k[base + d]; x2 = k[base + d + 32];
    k[base + d]      = x1 * c - x2 * ssn;
    k[base + d + 32] = x1 * ssn + x2 * c;
}

// ---------------- doc-tiled banded attention ----------------
// grid (NDOC, NH), 256 threads. One block stages the whole doc's K/V/Q for
// one head in smem, then each warp computes 32 queries (pairs at a time).
__global__ __launch_bounds__(256)
void attn_kernel(const float* __restrict__ q, const float* __restrict__ k,
                 const float* __restrict__ v, const int* __restrict__ tok_id,
                 float* __restrict__ o)
{
    extern __shared__ float sm[];
    float* Qs = sm;                      // [256][64]
    float* Ks = sm + 16384;              // [256][68]  (pad 68: conflict-free f4)
    float* Vs = Ks + 256 * 68;           // [256][64]
    float* Ps = Vs + 16384;              // [8][2][256]
    int*   Tk = (int*)(Ps + 8 * 2 * 256);// [256]

    const int doc = blockIdx.x, h = blockIdx.y;
    const int s0  = doc * 256;
    const int hb  = h * HD;
    const int tid = threadIdx.x, warp = tid >> 5, lane = tid & 31;

    Tk[tid] = tok_id[s0 + tid];
    for (int i = tid; i < 256 * 16; i += 256) {
        int row = i >> 4, c = (i & 15) * 4;
        size_t g = (size_t)(s0 + row) * DM + hb + c;
        *(float4*)&Qs[row * 64 + c] = *(const float4*)&q[g];
        *(float4*)&Ks[row * 68 + c] = *(const float4*)&k[g];
        *(float4*)&Vs[row * 64 + c] = *(const float4*)&v[g];
    }
    __syncthreads();

    float* Pw0 = Ps + warp * 512;
    float* Pw1 = Pw0 + 256;

    for (int qc = 0; qc < 16; qc++) {
        const int q0 = warp * 32 + qc * 2;
        const int q1 = q0 + 1;

        float sc0[8], sc1[8];
        #pragma unroll
        for (int m = 0; m < 8; m++) { sc0[m] = 0.f; sc1[m] = 0.f; }

        #pragma unroll
        for (int d4 = 0; d4 < 16; d4++) {
            float4 a0 = *(float4*)&Qs[q0 * 64 + d4 * 4];   // broadcast
            float4 a1 = *(float4*)&Qs[q1 * 64 + d4 * 4];
            #pragma unroll
            for (int m = 0; m < 8; m++) {
                float4 kv = *(float4*)&Ks[(m * 32 + lane) * 68 + d4 * 4];
                sc0[m] += a0.x*kv.x + a0.y*kv.y + a0.z*kv.z + a0.w*kv.w;
                sc1[m] += a1.x*kv.x + a1.y*kv.y + a1.z*kv.z + a1.w*kv.w;
            }
        }

        const int t0 = Tk[q0], t1 = Tk[q1];
        float m0 = -1e30f, m1 = -1e30f;
        #pragma unroll
        for (int m = 0; m < 8; m++) {
            int tj = Tk[m * 32 + lane];
            sc0[m] = (abs(t0 - tj) < 128) ? sc0[m] * 0.125f : -1e30f;
            sc1[m] = (abs(t1 - tj) < 128) ? sc1[m] * 0.125f : -1e30f;
            m0 = fmaxf(m0, sc0[m]);
            m1 = fmaxf(m1, sc1[m]);
        }
        #pragma unroll
        for (int off = 16; off; off >>= 1) {
            m0 = fmaxf(m0, __shfl_xor_sync(0xFFFFFFFFu, m0, off));
            m1 = fmaxf(m1, __shfl_xor_sync(0xFFFFFFFFu, m1, off));
        }

        float l0 = 0.f, l1 = 0.f;
        #pragma unroll
        for (int m = 0; m < 8; m++) {
            float e0 = (sc0[m] > -1e29f) ? expf(sc0[m] - m0) : 0.f;
            float e1 = (sc1[m] > -1e29f) ? expf(sc1[m] - m1) : 0.f;
            Pw0[m * 32 + lane] = e0;
            Pw1[m * 32 + lane] = e1;
            l0 += e0; l1 += e1;
        }
        #pragma unroll
        for (int off = 16; off; off >>= 1) {
            l0 += __shfl_xor_sync(0xFFFFFFFFu, l0, off);
            l1 += __shfl_xor_sync(0xFFFFFFFFu, l1, off);
        }
        __syncwarp();

        const float inv0 = 1.f / l0, inv1 = 1.f / l1;
        float a00 = 0.f, a01 = 0.f, a10 = 0.f, a11 = 0.f;
        for (int j = 0; j < 256; j++) {
            float p0 = Pw0[j], p1 = Pw1[j];      // broadcast
            float v0 = Vs[j * 64 + lane];        // conflict-free
            float v1 = Vs[j * 64 + lane + 32];
            a00 = fmaf(p0, v0, a00); a01 = fmaf(p0, v1, a01);
            a10 = fmaf(p1, v0, a10); a11 = fmaf(p1, v1, a11);
        }
        const size_t ob = (size_t)(s0 + q0) * DM + hb;
        o[ob + lane]           = a00 * inv0;
        o[ob + lane + 32]      = a01 * inv0;
        o[ob + DM + lane]      = a10 * inv1;
        o[ob + DM + lane + 32] = a11 * inv1;
        __syncwarp();
    }
}

// ---------------- SwiGLU gate: f1 = silu(f1) * f3 (float4) ----------------
__global__ void silu_mul_kernel(float* __restrict__ f1, const float* __restrict__ f3, int n4)
{
    int i = blockIdx.x * blockDim.x + threadIdx.x;
    if (i < n4) {
        float4 a = ((const float4*)f1)[i];
        float4 g = ((const float4*)f3)[i];
        a.x = (a.x / (1.0f + expf(-a.x))) * g.x;
        a.y = (a.y / (1.0f + expf(-a.y))) * g.y;
        a.z = (a.z / (1.0f + expf(-a.z))) * g.z;
        a.w = (a.w / (1.0f + expf(-a.w))) * g.w;
        ((float4*)f1)[i] = a;
    }
}

// ---------------- drivers ----------------
static inline void tgemm(const float* A, const float* B, float* C, const float* X,
                         int M, int N, int K, int mode)
{
    dim3 grid(N / 128, M / 128, 1);
    tgemm_kernel<<<grid, 256, SMEM_BYTES>>>(A, B, B, B, C, C, C, X, M, N, K, mode);
}
static inline void tgemm2(const float* A, const float* B0, const float* B1,
                          float* C0, float* C1, int M, int N, int K)
{
    dim3 grid(N / 128, M / 128, 2);
    tgemm_kernel<<<grid, 256, SMEM_BYTES>>>(A, B0, B1, B1, C0, C1, C1, nullptr, M, N, K, 0);
}
static inline void tgemm3(const float* A, const float* B0, const float* B1, const float* B2,
                          float* C0, float* C1, float* C2, int M, int N, int K)
{
    dim3 grid(N / 128, M / 128, 3);
    tgemm_kernel<<<grid, 256, SMEM_BYTES>>>(A, B0, B1, B2, C0, C1, C2, nullptr, M, N, K, 0);
}

extern "C" void kernel_launch(void* const* d_in, const int* in_sizes, int n_in,
                              void* d_out, int out_size)
{
    const float* x           = (const float*)d_in[0];
    const float* emb_w       = (const float*)d_in[1];
    const float* emb_b       = (const float*)d_in[2];
    const float* wq          = (const float*)d_in[3];
    const float* wk          = (const float*)d_in[4];
    const float* wv          = (const float*)d_in[5];
    const float* wo          = (const float*)d_in[6];
    const float* attn_norm_w = (const float*)d_in[7];
    const float* ffn_norm_w  = (const float*)d_in[8];
    const float* w1          = (const float*)d_in[9];
    const float* w2          = (const float*)d_in[10];
    const float* w3          = (const float*)d_in[11];
    const float* out_norm_w  = (const float*)d_in[12];
    const float* out_w       = (const float*)d_in[13];
    const int*   doc_id      = (const int*)d_in[14]; (void)doc_id;
    const int*   tok_id      = (const int*)d_in[15];
    float* out = (float*)d_out;

    cudaFuncSetAttribute(tgemm_kernel,
                         cudaFuncAttributeMaxDynamicSharedMemorySize, SMEM_BYTES);
    cudaFuncSetAttribute(attn_kernel,
                         cudaFuncAttributeMaxDynamicSharedMemorySize, ATTN_SMEM);

    float *h, *hn, *q, *k, *v, *o, *f1, *f3;
    cudaGetSymbolAddress((void**)&h,  g_h);
    cudaGetSymbolAddress((void**)&hn, g_hn);
    cudaGetSymbolAddress((void**)&q,  g_q);
    cudaGetSymbolAddress((void**)&k,  g_k);
    cudaGetSymbolAddress((void**)&v,  g_v);
    cudaGetSymbolAddress((void**)&o,  g_o);
    cudaGetSymbolAddress((void**)&f1, g_f1);
    cudaGetSymbolAddress((void**)&f3, g_f3);

    // embed: h = x @ emb_w + emb_b
    tgemm(x, emb_w, h, emb_b, SQ, DM, IND, 1);

    for (int l = 0; l < NL; l++) {
        const float* wq_l = wq + (size_t)l * DM * DM;
        const float* wk_l = wk + (size_t)l * DM * DM;
        const float* wv_l = wv + (size_t)l * DM * DM;
        const float* wo_l = wo + (size_t)l * DM * DM;
        const float* anw  = attn_norm_w + (size_t)l * DM;
        const float* fnw  = ffn_norm_w  + (size_t)l * DM;
        const float* w1_l = w1 + (size_t)l * DM * FF;
        const float* w2_l = w2 + (size_t)l * FF * DM;
        const float* w3_l = w3 + (size_t)l * DM * FF;

        rmsnorm_kernel<<<SQ, 256>>>(h, anw, hn);
        tgemm3(hn, wq_l, wk_l, wv_l, q, k, v, SQ, DM, DM);

        rope_kernel<<<SQ, 512>>>(q, k, tok_id);
        attn_kernel<<<dim3(NDOC, NH), 256, ATTN_SMEM>>>(q, k, v, tok_id, o);

        // h = h + o @ wo
        tgemm(o, wo_l, h, h, SQ, DM, DM, 2);

        rmsnorm_kernel<<<SQ, 256>>>(h, fnw, hn);
        tgemm2(hn, w1_l, w3_l, f1, f3, SQ, FF, DM);
        silu_mul_kernel<<<(SQ * FF / 4 + 255) / 256, 256>>>(f1, f3, SQ * FF / 4);
        // h = h + (silu(f1)*f3) @ w2
        tgemm(f1, w2_l, h, h, SQ, DM, FF, 2);
    }

    rmsnorm_kernel<<<SQ, 256>>>(h, out_norm_w, hn);
    tgemm(hn, out_w, out, nullptr, SQ, OUTD, DM, 0);
}